// round 1
// baseline (speedup 1.0000x reference)
#include <cuda_runtime.h>
#include <cstdint>

#define NN 100000
#define EE 1600000
#define DD 128
#define CC 100

// ---------------- scratch (static device globals; no runtime allocation) ----
__device__ int   g_mask_mode;           // 0=int32, 1=float32, 2=bytes
__device__ int   g_deg[NN];
__device__ float g_dis[NN];             // deg^{-1/2} (0 if deg==0)
__device__ float g_normA[EE];           // alpha * dis[src] * dis[dst]
__device__ __align__(128) float g_B1[(size_t)NN * DD];
__device__ __align__(128) float g_B2[(size_t)NN * DD];

// ---------------- mask dtype detection -------------------------------------
// Scans the first NN/4 32-bit words (safe under all three candidate layouts).
//  int32 0/1  -> every word in {0,1}
//  float 0/1  -> every word in {0, 0x3F800000}
//  bytes 0/1  -> words pack 4 bools; w.h.p. some word >1 and not float-like
__global__ void k_detect(const unsigned int* m) {
    __shared__ int s_gt1, s_nf;
    if (threadIdx.x == 0) { s_gt1 = 0; s_nf = 0; }
    __syncthreads();
    int gt1 = 0, nf = 0;
    for (int i = threadIdx.x; i < NN / 4; i += blockDim.x) {
        unsigned w = m[i];
        if (w > 1u) gt1 = 1;
        if (w != 0u && w != 0x3F800000u) nf = 1;
    }
    if (gt1) atomicOr(&s_gt1, 1);
    if (nf)  atomicOr(&s_nf, 1);
    __syncthreads();
    if (threadIdx.x == 0)
        g_mask_mode = (!s_gt1) ? 0 : ((!s_nf) ? 1 : 2);
}

__device__ __forceinline__ int read_mask(const void* m, int n) {
    int mode = g_mask_mode;
    if (mode == 0) return ((const int*)m)[n] != 0;
    if (mode == 1) return ((const float*)m)[n] != 0.0f;
    return ((const unsigned char*)m)[n] != 0;
}

// ---------------- degree / norm --------------------------------------------
__global__ void k_zero_deg() {
    int i = blockIdx.x * blockDim.x + threadIdx.x;
    if (i < NN) g_deg[i] = 0;
}

__global__ void k_deg(const int* __restrict__ dst) {
    int e = blockIdx.x * blockDim.x + threadIdx.x;
    if (e < EE) atomicAdd(&g_deg[dst[e]], 1);
}

__global__ void k_dis() {
    int i = blockIdx.x * blockDim.x + threadIdx.x;
    if (i < NN) {
        int d = g_deg[i];
        g_dis[i] = (d > 0) ? rsqrtf((float)d) : 0.0f;
    }
}

__global__ void k_norm(const int* __restrict__ src, const int* __restrict__ dst,
                       const float* __restrict__ alpha) {
    int e = blockIdx.x * blockDim.x + threadIdx.x;
    if (e < EE)
        g_normA[e] = alpha[0] * g_dis[src[e]] * g_dis[dst[e]];
}

// ---------------- init: out = res = (1-alpha) * y0 --------------------------
// Thread per float4 chunk: t = n*32 + lane
__global__ void k_init(float4* __restrict__ out,
                       const float* __restrict__ protos,
                       const int* __restrict__ labels,
                       const void* __restrict__ mask,
                       const float* __restrict__ alpha) {
    int t = blockIdx.x * blockDim.x + threadIdx.x;
    if (t >= NN * 32) return;
    int n = t >> 5, lane = t & 31;
    float4 v = make_float4(0.f, 0.f, 0.f, 0.f);
    if (read_mask(mask, n)) {
        float rc = 1.0f - alpha[0];
        const float4* p = (const float4*)(protos + (size_t)labels[n] * DD);
        v = p[lane];
        v.x *= rc; v.y *= rc; v.z *= rc; v.w *= rc;
    }
    out[t] = v;
}

__device__ __forceinline__ void red_add_v4(float* addr, float4 v) {
    asm volatile("red.global.add.v4.f32 [%0], {%1,%2,%3,%4};"
                 :: "l"(addr), "f"(v.x), "f"(v.y), "f"(v.z), "f"(v.w)
                 : "memory");
}

// ---------------- layer 1 scatter: y0 read straight from protos -------------
// Warp per edge, lane per float4 chunk.
__global__ void k_scatter1(float* __restrict__ out,
                           const int* __restrict__ src,
                           const int* __restrict__ dst,
                           const float* __restrict__ protos,
                           const int* __restrict__ labels,
                           const void* __restrict__ mask) {
    int w = (blockIdx.x * blockDim.x + threadIdx.x) >> 5;
    int lane = threadIdx.x & 31;
    if (w >= EE) return;
    float nw = g_normA[w];
    if (nw == 0.0f) return;
    int s = __ldg(&src[w]);
    if (!read_mask(mask, s)) return;          // y0 row is zero -> no-op
    int d = __ldg(&dst[w]);
    const float4* p = (const float4*)(protos + (size_t)labels[s] * DD);
    float4 v = p[lane];
    v.x *= nw; v.y *= nw; v.z *= nw; v.w *= nw;
    red_add_v4(out + (size_t)d * DD + lane * 4, v);
}

// ---------------- layers 2/3 scatter: gather with on-the-fly clamp ----------
__global__ void k_scatter(float* __restrict__ out,
                          const float* __restrict__ in,
                          const int* __restrict__ src,
                          const int* __restrict__ dst) {
    int w = (blockIdx.x * blockDim.x + threadIdx.x) >> 5;
    int lane = threadIdx.x & 31;
    if (w >= EE) return;
    float nw = g_normA[w];
    if (nw == 0.0f) return;
    int s = __ldg(&src[w]);
    int d = __ldg(&dst[w]);
    float4 v = ((const float4*)(in + (size_t)s * DD))[lane];
    v.x = fminf(fmaxf(v.x, 0.f), 1.f) * nw;
    v.y = fminf(fmaxf(v.y, 0.f), 1.f) * nw;
    v.z = fminf(fmaxf(v.z, 0.f), 1.f) * nw;
    v.w = fminf(fmaxf(v.w, 0.f), 1.f) * nw;
    red_add_v4(out + (size_t)d * DD + lane * 4, v);
}

// ---------------- final clamp on output (in-place) ---------------------------
__global__ void k_clamp(float4* __restrict__ o) {
    int i = blockIdx.x * blockDim.x + threadIdx.x;
    if (i < NN * 32) {
        float4 v = o[i];
        v.x = fminf(fmaxf(v.x, 0.f), 1.f);
        v.y = fminf(fmaxf(v.y, 0.f), 1.f);
        v.z = fminf(fmaxf(v.z, 0.f), 1.f);
        v.w = fminf(fmaxf(v.w, 0.f), 1.f);
        o[i] = v;
    }
}

// ---------------- launch -----------------------------------------------------
extern "C" void kernel_launch(void* const* d_in, const int* in_sizes, int n_in,
                              void* d_out, int out_size) {
    const void*  mask   = d_in[0];                       // bool [N] (dtype detected)
    const float* protos = (const float*)d_in[1];         // [C, D]
    const int*   labels = (const int*)d_in[2];           // [N]
    const int*   ei     = (const int*)d_in[3];           // [2, E]
    const float* alpha  = (const float*)d_in[4];         // scalar
    const int* src = ei;
    const int* dst = ei + EE;
    float* out = (float*)d_out;

    float* B1; cudaGetSymbolAddress((void**)&B1, g_B1);
    float* B2; cudaGetSymbolAddress((void**)&B2, g_B2);

    const int TB = 256;
    const int nodeBlocks  = (NN + TB - 1) / TB;
    const int edgeBlocks  = (EE + TB - 1) / TB;
    const int chunkBlocks = (NN * 32 + TB - 1) / TB;          // N*D/4 threads
    const long edgeWarpThreads = (long)EE * 32;
    const int edgeWarpBlocks = (int)((edgeWarpThreads + TB - 1) / TB);

    k_detect<<<1, 1024>>>((const unsigned int*)mask);
    k_zero_deg<<<nodeBlocks, TB>>>();
    k_deg<<<edgeBlocks, TB>>>(dst);
    k_dis<<<nodeBlocks, TB>>>();
    k_norm<<<edgeBlocks, TB>>>(src, dst, alpha);

    // layer 1: B1 = res; B1 += alpha*norm * y0[src]  (y0 from protos)
    k_init<<<chunkBlocks, TB>>>((float4*)B1, protos, labels, mask, alpha);
    k_scatter1<<<edgeWarpBlocks, TB>>>(B1, src, dst, protos, labels, mask);

    // layer 2: B2 = res; B2 += alpha*norm * clamp(B1)[src]
    k_init<<<chunkBlocks, TB>>>((float4*)B2, protos, labels, mask, alpha);
    k_scatter<<<edgeWarpBlocks, TB>>>(B2, B1, src, dst);

    // layer 3: out = res; out += alpha*norm * clamp(B2)[src]; out = clamp(out)
    k_init<<<chunkBlocks, TB>>>((float4*)out, protos, labels, mask, alpha);
    k_scatter<<<edgeWarpBlocks, TB>>>(out, B2, src, dst);
    k_clamp<<<chunkBlocks, TB>>>((float4*)out);
}

// round 2
// speedup vs baseline: 3.4353x; 3.4353x over previous
#include <cuda_runtime.h>
#include <cstdint>

#define NN 100000
#define EE 1600000
#define DD 128
#define CC 100

// ---------------- scratch (static device globals; no runtime allocation) ----
__device__ int   g_mask_mode;            // 0=int32, 1=float32, 2=bytes
__device__ int   g_deg[NN];
__device__ int   g_off[NN];
__device__ int   g_cur[NN];
__device__ float g_dis[NN];              // deg^{-1/2} (0 if deg==0)
__device__ int   g_counter;
__device__ __align__(16) int2  g_csr[EE];     // (src, bits(alpha*norm)) grouped by dst
__device__ int   g_lab[EE];                    // label of src, or -1 if unmasked
__device__ __align__(128) float g_B1[(size_t)NN * DD];
__device__ __align__(128) float g_B2[(size_t)NN * DD];

// ---------------- mask dtype detection -------------------------------------
__global__ void k_detect(const unsigned int* m) {
    __shared__ int s_gt1, s_nf;
    if (threadIdx.x == 0) { s_gt1 = 0; s_nf = 0; }
    __syncthreads();
    int gt1 = 0, nf = 0;
    for (int i = threadIdx.x; i < NN / 4; i += blockDim.x) {
        unsigned w = m[i];
        if (w > 1u) gt1 = 1;
        if (w != 0u && w != 0x3F800000u) nf = 1;
    }
    if (gt1) atomicOr(&s_gt1, 1);
    if (nf)  atomicOr(&s_nf, 1);
    __syncthreads();
    if (threadIdx.x == 0)
        g_mask_mode = (!s_gt1) ? 0 : ((!s_nf) ? 1 : 2);
}

__device__ __forceinline__ int read_mask(const void* m, int n) {
    int mode = g_mask_mode;
    if (mode == 0) return ((const int*)m)[n] != 0;
    if (mode == 1) return ((const float*)m)[n] != 0.0f;
    return ((const unsigned char*)m)[n] != 0;
}

// ---------------- CSR build --------------------------------------------------
__global__ void k_zero() {
    int i = blockIdx.x * blockDim.x + threadIdx.x;
    if (i < NN) g_deg[i] = 0;
    if (i == 0) g_counter = 0;
}

__global__ void k_deg(const int* __restrict__ dst) {
    int e = blockIdx.x * blockDim.x + threadIdx.x;
    if (e < EE) atomicAdd(&g_deg[dst[e]], 1);
}

// dis + disjoint contiguous range per node (order irrelevant for a pull-CSR)
__global__ void k_dis_off() {
    int i = blockIdx.x * blockDim.x + threadIdx.x;
    if (i < NN) {
        int d = g_deg[i];
        g_dis[i] = (d > 0) ? rsqrtf((float)d) : 0.0f;
        int o = atomicAdd(&g_counter, d);
        g_off[i] = o;
        g_cur[i] = o;
    }
}

__global__ void k_fill(const int* __restrict__ src, const int* __restrict__ dst,
                       const int* __restrict__ labels, const void* __restrict__ mask,
                       const float* __restrict__ alpha) {
    int e = blockIdx.x * blockDim.x + threadIdx.x;
    if (e >= EE) return;
    int s = src[e], d = dst[e];
    float nw = alpha[0] * g_dis[s] * g_dis[d];
    int p = atomicAdd(&g_cur[d], 1);
    g_csr[p] = make_int2(s, __float_as_int(nw));
    g_lab[p] = read_mask(mask, s) ? labels[s] : -1;
}

// ---------------- residual helper -------------------------------------------
__device__ __forceinline__ float4 residual(int n, int lane,
                                           const float4* __restrict__ protos4,
                                           const int* __restrict__ labels,
                                           const void* __restrict__ mask,
                                           float rc) {
    float4 r = make_float4(0.f, 0.f, 0.f, 0.f);
    if (read_mask(mask, n)) {
        float4 p = protos4[(size_t)labels[n] * 32 + lane];
        r.x = rc * p.x; r.y = rc * p.y; r.z = rc * p.z; r.w = rc * p.w;
    }
    return r;
}

__device__ __forceinline__ float clamp01(float x) {
    return fminf(fmaxf(x, 0.f), 1.f);
}

// ---------------- layer 1: gather from protos via label ---------------------
__global__ void k_gather1(float4* __restrict__ out,
                          const float4* __restrict__ protos4,
                          const int* __restrict__ labels,
                          const void* __restrict__ mask,
                          const float* __restrict__ alpha) {
    int w = (blockIdx.x * blockDim.x + threadIdx.x) >> 5;
    int lane = threadIdx.x & 31;
    if (w >= NN) return;
    int off = g_off[w], deg = g_deg[w];
    float4 acc = make_float4(0.f, 0.f, 0.f, 0.f);
    for (int base = 0; base < deg; base += 32) {
        int cnt = min(32, deg - base);
        int2 pr = make_int2(0, 0);
        int lb = -1;
        if (lane < cnt) { pr = g_csr[off + base + lane]; lb = g_lab[off + base + lane]; }
        for (int j = 0; j < cnt; j++) {
            int   l  = __shfl_sync(0xffffffffu, lb, j);
            float nw = __int_as_float(__shfl_sync(0xffffffffu, pr.y, j));
            if (l >= 0) {
                float4 v = protos4[(size_t)l * 32 + lane];
                acc.x += nw * v.x; acc.y += nw * v.y;
                acc.z += nw * v.z; acc.w += nw * v.w;
            }
        }
    }
    float rc = 1.0f - alpha[0];
    float4 r = residual(w, lane, protos4, labels, mask, rc);
    float4 o;
    o.x = clamp01(acc.x + r.x); o.y = clamp01(acc.y + r.y);
    o.z = clamp01(acc.z + r.z); o.w = clamp01(acc.w + r.w);
    out[(size_t)w * 32 + lane] = o;
}

// ---------------- layers 2/3: gather from previous (already clamped) --------
__global__ void k_gather(float4* __restrict__ out,
                         const float4* __restrict__ in,
                         const float4* __restrict__ protos4,
                         const int* __restrict__ labels,
                         const void* __restrict__ mask,
                         const float* __restrict__ alpha) {
    int w = (blockIdx.x * blockDim.x + threadIdx.x) >> 5;
    int lane = threadIdx.x & 31;
    if (w >= NN) return;
    int off = g_off[w], deg = g_deg[w];
    float4 acc = make_float4(0.f, 0.f, 0.f, 0.f);
    for (int base = 0; base < deg; base += 32) {
        int cnt = min(32, deg - base);
        int2 pr = make_int2(0, 0);
        if (lane < cnt) pr = g_csr[off + base + lane];
        #pragma unroll 4
        for (int j = 0; j < cnt; j++) {
            int   s  = __shfl_sync(0xffffffffu, pr.x, j);
            float nw = __int_as_float(__shfl_sync(0xffffffffu, pr.y, j));
            float4 v = in[(size_t)s * 32 + lane];
            acc.x += nw * v.x; acc.y += nw * v.y;
            acc.z += nw * v.z; acc.w += nw * v.w;
        }
    }
    float rc = 1.0f - alpha[0];
    float4 r = residual(w, lane, protos4, labels, mask, rc);
    float4 o;
    o.x = clamp01(acc.x + r.x); o.y = clamp01(acc.y + r.y);
    o.z = clamp01(acc.z + r.z); o.w = clamp01(acc.w + r.w);
    out[(size_t)w * 32 + lane] = o;
}

// ---------------- launch -----------------------------------------------------
extern "C" void kernel_launch(void* const* d_in, const int* in_sizes, int n_in,
                              void* d_out, int out_size) {
    const void*  mask   = d_in[0];                       // bool [N]
    const float* protos = (const float*)d_in[1];         // [C, D]
    const int*   labels = (const int*)d_in[2];           // [N]
    const int*   ei     = (const int*)d_in[3];           // [2, E]
    const float* alpha  = (const float*)d_in[4];         // scalar
    const int* src = ei;
    const int* dst = ei + EE;
    float* out = (float*)d_out;

    float* B1; cudaGetSymbolAddress((void**)&B1, g_B1);
    float* B2; cudaGetSymbolAddress((void**)&B2, g_B2);
    const float4* protos4 = (const float4*)protos;

    const int TB = 256;
    const int nodeBlocks = (NN + TB - 1) / TB;
    const int edgeBlocks = (EE + TB - 1) / TB;
    const int warpBlocks = (NN * 32 + TB - 1) / TB;   // warp per node

    k_detect<<<1, 1024>>>((const unsigned int*)mask);
    k_zero<<<nodeBlocks, TB>>>();
    k_deg<<<edgeBlocks, TB>>>(dst);
    k_dis_off<<<nodeBlocks, TB>>>();
    k_fill<<<edgeBlocks, TB>>>(src, dst, labels, mask, alpha);

    k_gather1<<<warpBlocks, TB>>>((float4*)B1, protos4, labels, mask, alpha);
    k_gather<<<warpBlocks, TB>>>((float4*)B2, (const float4*)B1, protos4, labels, mask, alpha);
    k_gather<<<warpBlocks, TB>>>((float4*)out, (const float4*)B2, protos4, labels, mask, alpha);
}

// round 3
// speedup vs baseline: 3.5886x; 1.0446x over previous
#include <cuda_runtime.h>
#include <cuda_fp16.h>
#include <cstdint>

#define NN 100000
#define EE 1600000
#define DD 128
#define CC 100

// ---------------- scratch (static device globals; no runtime allocation) ----
__device__ int   g_mask_mode;            // 0=int32, 1=float32, 2=bytes
__device__ int   g_deg[NN];
__device__ int   g_off[NN];
__device__ int   g_cur[NN];
__device__ float g_dis[NN];              // deg^{-1/2} (0 if deg==0)
__device__ int   g_counter;
__device__ __align__(16) int2  g_csr[EE];     // (src, bits(alpha*norm)) grouped by dst
__device__ int   g_lab[EE];                    // label of src, or -1 if unmasked
__device__ __align__(128) __half g_H1[(size_t)NN * DD];   // fp16 intermediates
__device__ __align__(128) __half g_H2[(size_t)NN * DD];

// ---------------- mask dtype detection -------------------------------------
__global__ void k_detect(const unsigned int* m) {
    __shared__ int s_gt1, s_nf;
    if (threadIdx.x == 0) { s_gt1 = 0; s_nf = 0; }
    __syncthreads();
    int gt1 = 0, nf = 0;
    for (int i = threadIdx.x; i < NN / 4; i += blockDim.x) {
        unsigned w = m[i];
        if (w > 1u) gt1 = 1;
        if (w != 0u && w != 0x3F800000u) nf = 1;
    }
    if (gt1) atomicOr(&s_gt1, 1);
    if (nf)  atomicOr(&s_nf, 1);
    __syncthreads();
    if (threadIdx.x == 0)
        g_mask_mode = (!s_gt1) ? 0 : ((!s_nf) ? 1 : 2);
}

__device__ __forceinline__ int read_mask(const void* m, int n) {
    int mode = g_mask_mode;
    if (mode == 0) return ((const int*)m)[n] != 0;
    if (mode == 1) return ((const float*)m)[n] != 0.0f;
    return ((const unsigned char*)m)[n] != 0;
}

// ---------------- CSR build --------------------------------------------------
__global__ void k_zero() {
    int i = blockIdx.x * blockDim.x + threadIdx.x;
    if (i < NN) g_deg[i] = 0;
    if (i == 0) g_counter = 0;
}

__global__ void k_deg(const int* __restrict__ dst) {
    int e = blockIdx.x * blockDim.x + threadIdx.x;
    if (e < EE) atomicAdd(&g_deg[dst[e]], 1);
}

// dis + disjoint contiguous range per node (order irrelevant for a pull-CSR)
__global__ void k_dis_off() {
    int i = blockIdx.x * blockDim.x + threadIdx.x;
    if (i < NN) {
        int d = g_deg[i];
        g_dis[i] = (d > 0) ? rsqrtf((float)d) : 0.0f;
        int o = atomicAdd(&g_counter, d);
        g_off[i] = o;
        g_cur[i] = o;
    }
}

__global__ void k_fill(const int* __restrict__ src, const int* __restrict__ dst,
                       const int* __restrict__ labels, const void* __restrict__ mask,
                       const float* __restrict__ alpha) {
    int e = blockIdx.x * blockDim.x + threadIdx.x;
    if (e >= EE) return;
    int s = src[e], d = dst[e];
    float nw = alpha[0] * g_dis[s] * g_dis[d];
    int p = atomicAdd(&g_cur[d], 1);
    g_csr[p] = make_int2(s, __float_as_int(nw));
    g_lab[p] = read_mask(mask, s) ? labels[s] : -1;
}

// ---------------- helpers ----------------------------------------------------
__device__ __forceinline__ float4 residual(int n, int lane,
                                           const float4* __restrict__ protos4,
                                           const int* __restrict__ labels,
                                           const void* __restrict__ mask,
                                           float rc) {
    float4 r = make_float4(0.f, 0.f, 0.f, 0.f);
    if (read_mask(mask, n)) {
        float4 p = protos4[(size_t)labels[n] * 32 + lane];
        r.x = rc * p.x; r.y = rc * p.y; r.z = rc * p.z; r.w = rc * p.w;
    }
    return r;
}

__device__ __forceinline__ float clamp01(float x) {
    return fminf(fmaxf(x, 0.f), 1.f);
}

__device__ __forceinline__ uint2 pack_half4(float4 o) {
    __half2 a = __floats2half2_rn(o.x, o.y);
    __half2 b = __floats2half2_rn(o.z, o.w);
    uint2 u;
    u.x = *reinterpret_cast<unsigned int*>(&a);
    u.y = *reinterpret_cast<unsigned int*>(&b);
    return u;
}

__device__ __forceinline__ float4 unpack_half4(uint2 u) {
    __half2 a = *reinterpret_cast<__half2*>(&u.x);
    __half2 b = *reinterpret_cast<__half2*>(&u.y);
    float2 fa = __half22float2(a);
    float2 fb = __half22float2(b);
    return make_float4(fa.x, fa.y, fb.x, fb.y);
}

// ---------------- layer 1: gather from protos via label, emit fp16 ----------
__global__ void k_gather1(uint2* __restrict__ out,
                          const float4* __restrict__ protos4,
                          const int* __restrict__ labels,
                          const void* __restrict__ mask,
                          const float* __restrict__ alpha) {
    int w = (blockIdx.x * blockDim.x + threadIdx.x) >> 5;
    int lane = threadIdx.x & 31;
    if (w >= NN) return;
    int off = g_off[w], deg = g_deg[w];
    float4 acc = make_float4(0.f, 0.f, 0.f, 0.f);
    for (int base = 0; base < deg; base += 32) {
        int cnt = min(32, deg - base);
        int2 pr = make_int2(0, 0);
        int lb = -1;
        if (lane < cnt) { pr = g_csr[off + base + lane]; lb = g_lab[off + base + lane]; }
        for (int j = 0; j < cnt; j++) {
            int   l  = __shfl_sync(0xffffffffu, lb, j);
            float nw = __int_as_float(__shfl_sync(0xffffffffu, pr.y, j));
            if (l >= 0) {
                float4 v = protos4[(size_t)l * 32 + lane];
                acc.x += nw * v.x; acc.y += nw * v.y;
                acc.z += nw * v.z; acc.w += nw * v.w;
            }
        }
    }
    float rc = 1.0f - alpha[0];
    float4 r = residual(w, lane, protos4, labels, mask, rc);
    float4 o;
    o.x = clamp01(acc.x + r.x); o.y = clamp01(acc.y + r.y);
    o.z = clamp01(acc.z + r.z); o.w = clamp01(acc.w + r.w);
    out[(size_t)w * 32 + lane] = pack_half4(o);
}

// ---------------- layer 2: fp16 in -> fp16 out -------------------------------
__global__ void k_gather_hh(uint2* __restrict__ out,
                            const uint2* __restrict__ in,
                            const float4* __restrict__ protos4,
                            const int* __restrict__ labels,
                            const void* __restrict__ mask,
                            const float* __restrict__ alpha) {
    int w = (blockIdx.x * blockDim.x + threadIdx.x) >> 5;
    int lane = threadIdx.x & 31;
    if (w >= NN) return;
    int off = g_off[w], deg = g_deg[w];
    float4 acc = make_float4(0.f, 0.f, 0.f, 0.f);
    for (int base = 0; base < deg; base += 32) {
        int cnt = min(32, deg - base);
        int2 pr = make_int2(0, 0);
        if (lane < cnt) pr = g_csr[off + base + lane];
        #pragma unroll 4
        for (int j = 0; j < cnt; j++) {
            int   s  = __shfl_sync(0xffffffffu, pr.x, j);
            float nw = __int_as_float(__shfl_sync(0xffffffffu, pr.y, j));
            float4 v = unpack_half4(in[(size_t)s * 32 + lane]);
            acc.x += nw * v.x; acc.y += nw * v.y;
            acc.z += nw * v.z; acc.w += nw * v.w;
        }
    }
    float rc = 1.0f - alpha[0];
    float4 r = residual(w, lane, protos4, labels, mask, rc);
    float4 o;
    o.x = clamp01(acc.x + r.x); o.y = clamp01(acc.y + r.y);
    o.z = clamp01(acc.z + r.z); o.w = clamp01(acc.w + r.w);
    out[(size_t)w * 32 + lane] = pack_half4(o);
}

// ---------------- layer 3: fp16 in -> fp32 out -------------------------------
__global__ void k_gather_hf(float4* __restrict__ out,
                            const uint2* __restrict__ in,
                            const float4* __restrict__ protos4,
                            const int* __restrict__ labels,
                            const void* __restrict__ mask,
                            const float* __restrict__ alpha) {
    int w = (blockIdx.x * blockDim.x + threadIdx.x) >> 5;
    int lane = threadIdx.x & 31;
    if (w >= NN) return;
    int off = g_off[w], deg = g_deg[w];
    float4 acc = make_float4(0.f, 0.f, 0.f, 0.f);
    for (int base = 0; base < deg; base += 32) {
        int cnt = min(32, deg - base);
        int2 pr = make_int2(0, 0);
        if (lane < cnt) pr = g_csr[off + base + lane];
        #pragma unroll 4
        for (int j = 0; j < cnt; j++) {
            int   s  = __shfl_sync(0xffffffffu, pr.x, j);
            float nw = __int_as_float(__shfl_sync(0xffffffffu, pr.y, j));
            float4 v = unpack_half4(in[(size_t)s * 32 + lane]);
            acc.x += nw * v.x; acc.y += nw * v.y;
            acc.z += nw * v.z; acc.w += nw * v.w;
        }
    }
    float rc = 1.0f - alpha[0];
    float4 r = residual(w, lane, protos4, labels, mask, rc);
    float4 o;
    o.x = clamp01(acc.x + r.x); o.y = clamp01(acc.y + r.y);
    o.z = clamp01(acc.z + r.z); o.w = clamp01(acc.w + r.w);
    out[(size_t)w * 32 + lane] = o;
}

// ---------------- launch -----------------------------------------------------
extern "C" void kernel_launch(void* const* d_in, const int* in_sizes, int n_in,
                              void* d_out, int out_size) {
    const void*  mask   = d_in[0];                       // bool [N]
    const float* protos = (const float*)d_in[1];         // [C, D]
    const int*   labels = (const int*)d_in[2];           // [N]
    const int*   ei     = (const int*)d_in[3];           // [2, E]
    const float* alpha  = (const float*)d_in[4];         // scalar
    const int* src = ei;
    const int* dst = ei + EE;
    float* out = (float*)d_out;

    __half* H1; cudaGetSymbolAddress((void**)&H1, g_H1);
    __half* H2; cudaGetSymbolAddress((void**)&H2, g_H2);
    const float4* protos4 = (const float4*)protos;

    const int TB = 256;
    const int nodeBlocks = (NN + TB - 1) / TB;
    const int edgeBlocks = (EE + TB - 1) / TB;
    const int warpBlocks = (NN * 32 + TB - 1) / TB;   // warp per node

    k_detect<<<1, 1024>>>((const unsigned int*)mask);
    k_zero<<<nodeBlocks, TB>>>();
    k_deg<<<edgeBlocks, TB>>>(dst);
    k_dis_off<<<nodeBlocks, TB>>>();
    k_fill<<<edgeBlocks, TB>>>(src, dst, labels, mask, alpha);

    k_gather1<<<warpBlocks, TB>>>((uint2*)H1, protos4, labels, mask, alpha);
    k_gather_hh<<<warpBlocks, TB>>>((uint2*)H2, (const uint2*)H1, protos4, labels, mask, alpha);
    k_gather_hf<<<warpBlocks, TB>>>((float4*)out, (const uint2*)H2, protos4, labels, mask, alpha);
}

// round 4
// speedup vs baseline: 3.9998x; 1.1146x over previous
#include <cuda_runtime.h>
#include <cuda_fp16.h>
#include <cstdint>

#define NN 100000
#define EE 1600000
#define DD 128
#define CC 100
#define CAP (EE + 8 * NN)     // padded CSR capacity

// ---------------- scratch (static device globals; no runtime allocation) ----
__device__ int   g_mask_mode;            // 0=int32, 1=float32, 2=bytes
__device__ int   g_deg[NN];
__device__ int   g_off[NN];
__device__ int   g_cur[NN];
__device__ float g_dis[NN];              // deg^{-1/2} (0 if deg==0)
__device__ int   g_counter;
__device__ __align__(16) int2 g_csr[CAP];   // (src, bits(alpha*norm)) grouped by dst, padded to 8
__device__ __align__(16) int  g_lab[CAP];   // label of src, or -1 if unmasked/dummy
__device__ __align__(128) __half g_H1[(size_t)NN * DD];   // fp16 intermediates
__device__ __align__(128) __half g_H2[(size_t)NN * DD];

// ---------------- mask dtype detection -------------------------------------
__global__ void k_detect(const unsigned int* m) {
    __shared__ int s_gt1, s_nf;
    if (threadIdx.x == 0) { s_gt1 = 0; s_nf = 0; }
    __syncthreads();
    int gt1 = 0, nf = 0;
    for (int i = threadIdx.x; i < NN / 4; i += blockDim.x) {
        unsigned w = m[i];
        if (w > 1u) gt1 = 1;
        if (w != 0u && w != 0x3F800000u) nf = 1;
    }
    if (gt1) atomicOr(&s_gt1, 1);
    if (nf)  atomicOr(&s_nf, 1);
    __syncthreads();
    if (threadIdx.x == 0)
        g_mask_mode = (!s_gt1) ? 0 : ((!s_nf) ? 1 : 2);
}

__device__ __forceinline__ int read_mask(const void* m, int n) {
    int mode = g_mask_mode;
    if (mode == 0) return ((const int*)m)[n] != 0;
    if (mode == 1) return ((const float*)m)[n] != 0.0f;
    return ((const unsigned char*)m)[n] != 0;
}

// ---------------- CSR build --------------------------------------------------
__global__ void k_zero() {
    int i = blockIdx.x * blockDim.x + threadIdx.x;
    if (i < NN) g_deg[i] = 0;
    if (i == 0) g_counter = 0;
}

__global__ void k_deg(const int* __restrict__ dst) {
    int e = blockIdx.x * blockDim.x + threadIdx.x;
    if (e < EE) atomicAdd(&g_deg[dst[e]], 1);
}

// dis + disjoint contiguous 8-padded range per node
__global__ void k_dis_off() {
    int i = blockIdx.x * blockDim.x + threadIdx.x;
    if (i < NN) {
        int d = g_deg[i];
        g_dis[i] = (d > 0) ? rsqrtf((float)d) : 0.0f;
        int dp = (d + 7) & ~7;
        int o = atomicAdd(&g_counter, dp);
        g_off[i] = o;
        g_cur[i] = o;
    }
}

// fill the padded tail [off+deg, off+degP) with dummy entries
__global__ void k_pad() {
    int i = blockIdx.x * blockDim.x + threadIdx.x;
    if (i >= NN) return;
    int d = g_deg[i], o = g_off[i];
    int dp = (d + 7) & ~7;
    for (int p = o + d; p < o + dp; p++) {
        g_csr[p] = make_int2(0, 0);      // src 0, weight 0
        g_lab[p] = -1;
    }
}

__global__ void k_fill(const int* __restrict__ src, const int* __restrict__ dst,
                       const int* __restrict__ labels, const void* __restrict__ mask,
                       const float* __restrict__ alpha) {
    int e = blockIdx.x * blockDim.x + threadIdx.x;
    if (e >= EE) return;
    int s = src[e], d = dst[e];
    float nw = alpha[0] * g_dis[s] * g_dis[d];
    int p = atomicAdd(&g_cur[d], 1);
    g_csr[p] = make_int2(s, __float_as_int(nw));
    g_lab[p] = read_mask(mask, s) ? labels[s] : -1;
}

// ---------------- helpers ----------------------------------------------------
__device__ __forceinline__ float4 residual(int n, int lane,
                                           const float4* __restrict__ protos4,
                                           const int* __restrict__ labels,
                                           const void* __restrict__ mask,
                                           float rc) {
    float4 r = make_float4(0.f, 0.f, 0.f, 0.f);
    if (read_mask(mask, n)) {
        float4 p = protos4[(size_t)labels[n] * 32 + lane];
        r.x = rc * p.x; r.y = rc * p.y; r.z = rc * p.z; r.w = rc * p.w;
    }
    return r;
}

__device__ __forceinline__ float clamp01(float x) {
    return fminf(fmaxf(x, 0.f), 1.f);
}

__device__ __forceinline__ uint2 pack_half4(float4 o) {
    __half2 a = __floats2half2_rn(o.x, o.y);
    __half2 b = __floats2half2_rn(o.z, o.w);
    uint2 u;
    u.x = *reinterpret_cast<unsigned int*>(&a);
    u.y = *reinterpret_cast<unsigned int*>(&b);
    return u;
}

__device__ __forceinline__ float4 unpack_half4(uint2 u) {
    __half2 a = *reinterpret_cast<__half2*>(&u.x);
    __half2 b = *reinterpret_cast<__half2*>(&u.y);
    float2 fa = __half22float2(a);
    float2 fb = __half22float2(b);
    return make_float4(fa.x, fa.y, fb.x, fb.y);
}

// ---------------- layer 1: gather from protos via label, emit fp16 ----------
__global__ void k_gather1(uint2* __restrict__ out,
                          const float4* __restrict__ protos4,
                          const int* __restrict__ labels,
                          const void* __restrict__ mask,
                          const float* __restrict__ alpha) {
    int w = (blockIdx.x * blockDim.x + threadIdx.x) >> 5;
    int lane = threadIdx.x & 31;
    if (w >= NN) return;
    int off = g_off[w];
    int degP = (g_deg[w] + 7) & ~7;
    const int4* cp = (const int4*)(g_csr + off);     // 16B aligned (off multiple of 8)
    const int4* lp = (const int4*)(g_lab + off);
    float4 acc = make_float4(0.f, 0.f, 0.f, 0.f);
    for (int base = 0; base < degP; base += 8) {
        int4 c01 = cp[base / 2 + 0];   // entries 0,1 : (s0,n0,s1,n1)
        int4 c23 = cp[base / 2 + 1];
        int4 c45 = cp[base / 2 + 2];
        int4 c67 = cp[base / 2 + 3];
        int4 l03 = lp[base / 4 + 0];   // labels 0..3
        int4 l47 = lp[base / 4 + 1];
        int   lb[8] = { l03.x, l03.y, l03.z, l03.w, l47.x, l47.y, l47.z, l47.w };
        float nw[8] = { __int_as_float(c01.y), __int_as_float(c01.w),
                        __int_as_float(c23.y), __int_as_float(c23.w),
                        __int_as_float(c45.y), __int_as_float(c45.w),
                        __int_as_float(c67.y), __int_as_float(c67.w) };
        #pragma unroll
        for (int j = 0; j < 8; j++) {
            if (lb[j] >= 0) {
                float4 v = protos4[(size_t)lb[j] * 32 + lane];
                acc.x += nw[j] * v.x; acc.y += nw[j] * v.y;
                acc.z += nw[j] * v.z; acc.w += nw[j] * v.w;
            }
        }
    }
    float rc = 1.0f - alpha[0];
    float4 r = residual(w, lane, protos4, labels, mask, rc);
    float4 o;
    o.x = clamp01(acc.x + r.x); o.y = clamp01(acc.y + r.y);
    o.z = clamp01(acc.z + r.z); o.w = clamp01(acc.w + r.w);
    out[(size_t)w * 32 + lane] = pack_half4(o);
}

// ---------------- layers 2/3 core: fp16 in, fp32 accumulate -----------------
__device__ __forceinline__ float4 gather_core(int w, int lane,
                                              const uint2* __restrict__ in) {
    int off = g_off[w];
    int degP = (g_deg[w] + 7) & ~7;
    const int4* cp = (const int4*)(g_csr + off);
    const uint2* inl = in + lane;
    float4 acc = make_float4(0.f, 0.f, 0.f, 0.f);
    for (int base = 0; base < degP; base += 8) {
        int4 c01 = cp[base / 2 + 0];
        int4 c23 = cp[base / 2 + 1];
        int4 c45 = cp[base / 2 + 2];
        int4 c67 = cp[base / 2 + 3];
        int   sr[8] = { c01.x, c01.z, c23.x, c23.z, c45.x, c45.z, c67.x, c67.z };
        float nw[8] = { __int_as_float(c01.y), __int_as_float(c01.w),
                        __int_as_float(c23.y), __int_as_float(c23.w),
                        __int_as_float(c45.y), __int_as_float(c45.w),
                        __int_as_float(c67.y), __int_as_float(c67.w) };
        float4 v[8];
        #pragma unroll
        for (int j = 0; j < 8; j++)
            v[j] = unpack_half4(inl[(size_t)sr[j] * 32]);
        #pragma unroll
        for (int j = 0; j < 8; j++) {
            acc.x += nw[j] * v[j].x; acc.y += nw[j] * v[j].y;
            acc.z += nw[j] * v[j].z; acc.w += nw[j] * v[j].w;
        }
    }
    return acc;
}

__global__ void k_gather_hh(uint2* __restrict__ out,
                            const uint2* __restrict__ in,
                            const float4* __restrict__ protos4,
                            const int* __restrict__ labels,
                            const void* __restrict__ mask,
                            const float* __restrict__ alpha) {
    int w = (blockIdx.x * blockDim.x + threadIdx.x) >> 5;
    int lane = threadIdx.x & 31;
    if (w >= NN) return;
    float4 acc = gather_core(w, lane, in);
    float rc = 1.0f - alpha[0];
    float4 r = residual(w, lane, protos4, labels, mask, rc);
    float4 o;
    o.x = clamp01(acc.x + r.x); o.y = clamp01(acc.y + r.y);
    o.z = clamp01(acc.z + r.z); o.w = clamp01(acc.w + r.w);
    out[(size_t)w * 32 + lane] = pack_half4(o);
}

__global__ void k_gather_hf(float4* __restrict__ out,
                            const uint2* __restrict__ in,
                            const float4* __restrict__ protos4,
                            const int* __restrict__ labels,
                            const void* __restrict__ mask,
                            const float* __restrict__ alpha) {
    int w = (blockIdx.x * blockDim.x + threadIdx.x) >> 5;
    int lane = threadIdx.x & 31;
    if (w >= NN) return;
    float4 acc = gather_core(w, lane, in);
    float rc = 1.0f - alpha[0];
    float4 r = residual(w, lane, protos4, labels, mask, rc);
    float4 o;
    o.x = clamp01(acc.x + r.x); o.y = clamp01(acc.y + r.y);
    o.z = clamp01(acc.z + r.z); o.w = clamp01(acc.w + r.w);
    out[(size_t)w * 32 + lane] = o;
}

// ---------------- launch -----------------------------------------------------
extern "C" void kernel_launch(void* const* d_in, const int* in_sizes, int n_in,
                              void* d_out, int out_size) {
    const void*  mask   = d_in[0];                       // bool [N]
    const float* protos = (const float*)d_in[1];         // [C, D]
    const int*   labels = (const int*)d_in[2];           // [N]
    const int*   ei     = (const int*)d_in[3];           // [2, E]
    const float* alpha  = (const float*)d_in[4];         // scalar
    const int* src = ei;
    const int* dst = ei + EE;
    float* out = (float*)d_out;

    __half* H1; cudaGetSymbolAddress((void**)&H1, g_H1);
    __half* H2; cudaGetSymbolAddress((void**)&H2, g_H2);
    const float4* protos4 = (const float4*)protos;

    const int TB = 256;
    const int nodeBlocks = (NN + TB - 1) / TB;
    const int edgeBlocks = (EE + TB - 1) / TB;
    const int warpBlocks = (NN * 32 + TB - 1) / TB;   // warp per node

    k_detect<<<1, 1024>>>((const unsigned int*)mask);
    k_zero<<<nodeBlocks, TB>>>();
    k_deg<<<edgeBlocks, TB>>>(dst);
    k_dis_off<<<nodeBlocks, TB>>>();
    k_pad<<<nodeBlocks, TB>>>();
    k_fill<<<edgeBlocks, TB>>>(src, dst, labels, mask, alpha);

    k_gather1<<<warpBlocks, TB>>>((uint2*)H1, protos4, labels, mask, alpha);
    k_gather_hh<<<warpBlocks, TB>>>((uint2*)H2, (const uint2*)H1, protos4, labels, mask, alpha);
    k_gather_hf<<<warpBlocks, TB>>>((float4*)out, (const uint2*)H2, protos4, labels, mask, alpha);
}